// round 5
// baseline (speedup 1.0000x reference)
#include <cuda_runtime.h>

// ---------------- problem constants (fixed by the dataset) ----------------
#define NN    50000
#define EE    640000
#define HH    4
#define CC    32
#define RR    8
#define HC    128           // H*C
#define RNSEG (RR*NN)       // 400000 segments
#define QKVP  96            // q|k|v packed columns
#define NB1   391           // ceil(RNSEG/1024) scan blocks

// ---------------- device scratch (static: no runtime allocation) ----------
__device__ __align__(16) float g_hj  [NN*HC];      // x @ Wj           25.6 MB
__device__ __align__(16) float g_hi  [NN*HC];      // x @ Wi           25.6 MB
__device__ __align__(16) float g_sn  [NN*HC];      // x @ W_self_node  25.6 MB
__device__ __align__(16) float g_self[NN*CC];      // x @ W_self        6.4 MB
__device__ __align__(16) float g_z   [RR*NN*HC];   // z = agg + sn    204.8 MB
__device__ __align__(16) float g_qkvb[RR*NN*QKVP]; // q|k|v           153.6 MB
__device__ __align__(16) float g_wcat[RR*HC*QKVP]; // packed Wq|Wk|Wv
__device__ int   g_cnt   [RNSEG];
__device__ int   g_start [RNSEG];
__device__ int   g_cursor[RNSEG];
__device__ int   g_ssrc  [EE];                     // src node per sorted edge slot
__device__ int   g_bsum  [512];
__device__ int   g_ei64;                           // edge_index stored as int64?
__device__ int   g_et64;                           // edge_type  stored as int64?

// ---------------- dtype sniffing ------------------------------------------
// Under default JAX config, jnp.int64 silently becomes int32. Values are
// nonnegative < 2^31, so an int64 buffer has every odd 32-bit word == 0.
// For int32 edge_type in [0,8), 128 consecutive zeros at odd slots has
// probability 8^-128 ~= 0. Single-thread kernel, negligible cost.
__global__ void k_detect(const int* __restrict__ ei_raw,
                         const int* __restrict__ et_raw)
{
    int a = 1, b = 1;
    for (int i = 0; i < 128; i++) {
        if (ei_raw[2 * i + 1] != 0) a = 0;
        if (et_raw[2 * i + 1] != 0) b = 0;
    }
    g_ei64 = a;
    g_et64 = b;
}

// Load logical element i from an index buffer that may be i32 or i64.
__device__ __forceinline__ int load_idx(const int* __restrict__ p, int i, int is64)
{
    return is64 ? p[2 * i] : p[i];     // little-endian low word
}

// ---------------- generic K=128 SGEMM: C[M,P] = A[M,128] @ B[128,P] -------
// BM=128, BN=64, BK=32, 128 threads, 8x8 register tile. Batched via blockIdx.z.
__global__ __launch_bounds__(128)
void sgemm128k(const float* __restrict__ A, const float* __restrict__ B,
               float* __restrict__ C, int M, int P,
               long long sA, long long sB, long long sC)
{
    A += (long long)blockIdx.z * sA;
    B += (long long)blockIdx.z * sB;
    C += (long long)blockIdx.z * sC;

    __shared__ __align__(16) float As[128][33];   // padded: conflict-free a reads
    __shared__ __align__(16) float Bs[32][64];

    const int tid = threadIdx.x;
    const int tx  = tid & 7;          // 0..7  -> 8 cols each
    const int ty  = tid >> 3;         // 0..15 -> 8 rows each
    const int m0  = blockIdx.y * 128;
    const int n0  = blockIdx.x * 64;

    float acc[8][8];
#pragma unroll
    for (int i = 0; i < 8; i++)
#pragma unroll
        for (int j = 0; j < 8; j++) acc[i][j] = 0.f;

    for (int kc = 0; kc < 128; kc += 32) {
        // stage A tile [128 rows][32 k]
#pragma unroll
        for (int i = 0; i < 8; i++) {
            int idx = i * 128 + tid;            // 0..1023 float4 slots
            int row = idx >> 3, kq = idx & 7;
            float4 v = make_float4(0.f, 0.f, 0.f, 0.f);
            if (m0 + row < M)
                v = *(const float4*)(A + (long long)(m0 + row) * 128 + kc + kq * 4);
            As[row][kq * 4 + 0] = v.x;
            As[row][kq * 4 + 1] = v.y;
            As[row][kq * 4 + 2] = v.z;
            As[row][kq * 4 + 3] = v.w;
        }
        // stage B tile [32 k][64 cols] (column-guarded for P=96 / P=32)
#pragma unroll
        for (int i = 0; i < 4; i++) {
            int idx = i * 128 + tid;            // 0..511 float4 slots
            int brow = idx >> 4, bq = idx & 15;
            int c0 = n0 + bq * 4;
            float4 v = make_float4(0.f, 0.f, 0.f, 0.f);
            const float* brp = B + (long long)(kc + brow) * P;
            if (c0 + 3 < P) {
                v = *(const float4*)(brp + c0);
            } else {
                if (c0 + 0 < P) v.x = brp[c0 + 0];
                if (c0 + 1 < P) v.y = brp[c0 + 1];
                if (c0 + 2 < P) v.z = brp[c0 + 2];
                if (c0 + 3 < P) v.w = brp[c0 + 3];
            }
            *(float4*)&Bs[brow][bq * 4] = v;
        }
        __syncthreads();

#pragma unroll 4
        for (int k = 0; k < 32; k++) {
            float a[8];
#pragma unroll
            for (int i = 0; i < 8; i++) a[i] = As[ty * 8 + i][k];
            float4 b0 = *(const float4*)&Bs[k][tx * 8];
            float4 b1 = *(const float4*)&Bs[k][tx * 8 + 4];
            float b[8] = { b0.x, b0.y, b0.z, b0.w, b1.x, b1.y, b1.z, b1.w };
#pragma unroll
            for (int i = 0; i < 8; i++)
#pragma unroll
                for (int j = 0; j < 8; j++) acc[i][j] += a[i] * b[j];
        }
        __syncthreads();
    }

    // epilogue
#pragma unroll
    for (int i = 0; i < 8; i++) {
        int grow = m0 + ty * 8 + i;
        if (grow >= M) continue;
        int c0 = n0 + tx * 8;
        float* crow = C + (long long)grow * P;
        if (c0 + 7 < P) {
            float4 v0 = make_float4(acc[i][0], acc[i][1], acc[i][2], acc[i][3]);
            float4 v1 = make_float4(acc[i][4], acc[i][5], acc[i][6], acc[i][7]);
            *(float4*)(crow + c0)     = v0;
            *(float4*)(crow + c0 + 4) = v1;
        } else {
#pragma unroll
            for (int j = 0; j < 8; j++)
                if (c0 + j < P) crow[c0 + j] = acc[i][j];
        }
    }
}

// ---------------- pack Wq|Wk|Wv -> [R][128][96] ---------------------------
__global__ void k_pack(const float* __restrict__ Wq, const float* __restrict__ Wk,
                       const float* __restrict__ Wv)
{
    int idx = blockIdx.x * blockDim.x + threadIdx.x;
    if (idx >= RR * HC * QKVP) return;
    int j  = idx % QKVP;
    int rd = idx / QKVP;           // r*128 + d
    float v;
    if      (j < 32) v = Wq[rd * 32 + j];
    else if (j < 64) v = Wk[rd * 32 + (j - 32)];
    else             v = Wv[rd * 32 + (j - 64)];
    g_wcat[idx] = v;
}

// ---------------- counting sort of edges by segment -----------------------
__global__ void k_zero()
{
    int i = blockIdx.x * blockDim.x + threadIdx.x;
    if (i < RNSEG) { g_cnt[i] = 0; g_cursor[i] = 0; }
}

__global__ void k_hist(const int* __restrict__ ei, const int* __restrict__ et)
{
    int e = blockIdx.x * blockDim.x + threadIdx.x;
    if (e >= EE) return;
    int i64 = g_ei64, t64 = g_et64;
    int dst = load_idx(ei, EE + e, i64);
    int r   = load_idx(et, e, t64);
    atomicAdd(&g_cnt[r * NN + dst], 1);
}

__global__ void k_scan1()
{
    __shared__ int sh[256];
    int t = threadIdx.x;
    int base = blockIdx.x * 1024 + t * 4;
    int v0 = 0, v1 = 0, v2 = 0, v3 = 0;
    if (base + 0 < RNSEG) v0 = g_cnt[base + 0];
    if (base + 1 < RNSEG) v1 = g_cnt[base + 1];
    if (base + 2 < RNSEG) v2 = g_cnt[base + 2];
    if (base + 3 < RNSEG) v3 = g_cnt[base + 3];
    int local = v0 + v1 + v2 + v3;
    sh[t] = local;
    __syncthreads();
    for (int off = 1; off < 256; off <<= 1) {
        int x = 0;
        if (t >= off) x = sh[t - off];
        __syncthreads();
        if (t >= off) sh[t] += x;
        __syncthreads();
    }
    int run = sh[t] - local;   // exclusive prefix within block
    if (base + 0 < RNSEG) g_start[base + 0] = run;       run += v0;
    if (base + 1 < RNSEG) g_start[base + 1] = run;       run += v1;
    if (base + 2 < RNSEG) g_start[base + 2] = run;       run += v2;
    if (base + 3 < RNSEG) g_start[base + 3] = run;
    if (t == 255) g_bsum[blockIdx.x] = sh[255];
}

__global__ void k_scan2(int nb)
{
    __shared__ int sh[512];
    int t = threadIdx.x;
    int val = (t < nb) ? g_bsum[t] : 0;
    sh[t] = val;
    __syncthreads();
    for (int off = 1; off < 512; off <<= 1) {
        int x = 0;
        if (t >= off) x = sh[t - off];
        __syncthreads();
        if (t >= off) sh[t] += x;
        __syncthreads();
    }
    if (t < nb) g_bsum[t] = sh[t] - val;   // exclusive
}

__global__ void k_scan3()
{
    int i = blockIdx.x * blockDim.x + threadIdx.x;
    if (i < RNSEG) g_start[i] += g_bsum[i >> 10];
}

__global__ void k_scatter(const int* __restrict__ ei, const int* __restrict__ et)
{
    int e = blockIdx.x * blockDim.x + threadIdx.x;
    if (e >= EE) return;
    int i64 = g_ei64, t64 = g_et64;
    int src = load_idx(ei, e, i64);
    int dst = load_idx(ei, EE + e, i64);
    int r   = load_idx(et, e, t64);
    int seg = r * NN + dst;
    int pos = g_start[seg] + atomicAdd(&g_cursor[seg], 1);
    g_ssrc[pos] = src;
}

// ---------------- per-segment softmax-weighted aggregation ----------------
// One warp per segment (r,n). lane -> 4 consecutive feature dims (d0=lane*4),
// head h = lane>>3. Writes z[seg] = sn[n] + sum_e a(e,h) * h_j[src] directly.
__global__ void k_agg(const float* __restrict__ natt)
{
    int w    = (blockIdx.x * blockDim.x + threadIdx.x) >> 5;
    int lane = threadIdx.x & 31;
    if (w >= RNSEG) return;
    int r  = w / NN;
    int n  = w - r * NN;
    int d0 = lane * 4;

    float4 sn4 = *(const float4*)(g_sn + n * HC + d0);
    float4 acc = make_float4(0.f, 0.f, 0.f, 0.f);
    int cnt = g_cnt[w];

    if (cnt > 0) {
        int st = g_start[w];
        float4 xi = *(const float4*)(g_hi + n * HC + d0);
        int h  = lane >> 3;
        int cb = (lane & 7) * 4;
        const float* ab = natt + (r * HH + h) * (2 * CC);
        float4 ai = *(const float4*)(ab + cb);
        float4 aj = *(const float4*)(ab + CC + cb);

        float pi = ai.x * xi.x + ai.y * xi.y + ai.z * xi.z + ai.w * xi.w;
        pi += __shfl_xor_sync(0xffffffffu, pi, 1);
        pi += __shfl_xor_sync(0xffffffffu, pi, 2);
        pi += __shfl_xor_sync(0xffffffffu, pi, 4);   // att_i . x_i for head h

        float denom = 0.f;
        for (int j = 0; j < cnt; j++) {
            int src = g_ssrc[st + j];
            float4 xj = *(const float4*)(g_hj + src * HC + d0);
            float pj = aj.x * xj.x + aj.y * xj.y + aj.z * xj.z + aj.w * xj.w;
            pj += __shfl_xor_sync(0xffffffffu, pj, 1);
            pj += __shfl_xor_sync(0xffffffffu, pj, 2);
            pj += __shfl_xor_sync(0xffffffffu, pj, 4);
            float al = pi + pj;
            al = (al > 0.f) ? al : 0.2f * al;        // leaky relu
            denom += __expf(al);
        }
        float inv = 1.f / (denom + 1e-16f);
        for (int j = 0; j < cnt; j++) {
            int src = g_ssrc[st + j];
            float4 xj = *(const float4*)(g_hj + src * HC + d0);
            float pj = aj.x * xj.x + aj.y * xj.y + aj.z * xj.z + aj.w * xj.w;
            pj += __shfl_xor_sync(0xffffffffu, pj, 1);
            pj += __shfl_xor_sync(0xffffffffu, pj, 2);
            pj += __shfl_xor_sync(0xffffffffu, pj, 4);
            float al = pi + pj;
            al = (al > 0.f) ? al : 0.2f * al;
            float a = __expf(al) * inv;
            acc.x += a * xj.x; acc.y += a * xj.y;
            acc.z += a * xj.z; acc.w += a * xj.w;
        }
    }
    float4 zv = make_float4(sn4.x + acc.x, sn4.y + acc.y,
                            sn4.z + acc.z, sn4.w + acc.w);
    *(float4*)(g_z + (long long)w * HC + d0) = zv;
}

// ---------------- relation-level attention + output -----------------------
// One warp per node, lane = channel c (0..31).
__global__ void k_final(const float* __restrict__ wrel, float* __restrict__ out)
{
    int n    = (blockIdx.x * blockDim.x + threadIdx.x) >> 5;
    int lane = threadIdx.x & 31;
    if (n >= NN) return;

    float q[RR], kk[RR], vv[RR];
#pragma unroll
    for (int r = 0; r < RR; r++) {
        const float* p = g_qkvb + ((long long)r * NN + n) * QKVP;
        q[r]  = p[lane];
        kk[r] = p[32 + lane];
        vv[r] = p[64 + lane];
    }
    float selfc = g_self[n * CC + lane];
    float o = 0.f;

#pragma unroll
    for (int r = 0; r < RR; r++) {
        float t[RR];
#pragma unroll
        for (int s = 0; s < RR; s++) t[s] = q[r] * kk[s];
#pragma unroll
        for (int off = 16; off > 0; off >>= 1)
#pragma unroll
            for (int s = 0; s < RR; s++)
                t[s] += __shfl_xor_sync(0xffffffffu, t[s], off);
        float m = t[0];
#pragma unroll
        for (int s = 1; s < RR; s++) m = fmaxf(m, t[s]);
        float psum = 0.f, dacc = 0.f;
#pragma unroll
        for (int s = 0; s < RR; s++) {
            float e = __expf(t[s] - m);
            psum += e;
            dacc += e * vv[s];
        }
        float delta = dacc / psum;
        float sd = delta;
#pragma unroll
        for (int off = 16; off > 0; off >>= 1)
            sd += __shfl_xor_sync(0xffffffffu, sd, off);
        float mask = (sd != 0.f) ? 1.f : 0.f;
        o += (delta + selfc * mask) * wrel[r];
    }
    out[n * CC + lane] = o;
}

// ---------------- host launcher -------------------------------------------
extern "C" void kernel_launch(void* const* d_in, const int* in_sizes, int n_in,
                              void* d_out, int out_size)
{
    (void)in_sizes; (void)n_in; (void)out_size;
    const float* x    = (const float*)d_in[0];
    const int*   ei   = (const int*)d_in[1];    // int32 OR int64 (sniffed)
    const int*   et   = (const int*)d_in[2];    // int32 OR int64 (sniffed)
    const float* Wj   = (const float*)d_in[3];
    const float* Wi   = (const float*)d_in[4];
    const float* natt = (const float*)d_in[5];
    const float* Wq   = (const float*)d_in[6];
    const float* Wk   = (const float*)d_in[7];
    const float* Wv   = (const float*)d_in[8];
    const float* Wself= (const float*)d_in[9];
    const float* Wsn  = (const float*)d_in[10];
    const float* Wrel = (const float*)d_in[11];
    float*       out  = (float*)d_out;

    float *hj, *hi, *sn, *self_, *z, *qkv, *wcat;
    cudaGetSymbolAddress((void**)&hj,   g_hj);
    cudaGetSymbolAddress((void**)&hi,   g_hi);
    cudaGetSymbolAddress((void**)&sn,   g_sn);
    cudaGetSymbolAddress((void**)&self_,g_self);
    cudaGetSymbolAddress((void**)&z,    g_z);
    cudaGetSymbolAddress((void**)&qkv,  g_qkvb);
    cudaGetSymbolAddress((void**)&wcat, g_wcat);

    const int MBLK = (NN + 127) / 128;   // 391

    // index dtype sniffing (must precede k_hist/k_scatter)
    k_detect<<<1, 1>>>(ei, et);

    // node projections
    sgemm128k<<<dim3(2, MBLK, 1), 128>>>(x, Wj,    hj,    NN, 128, 0, 0, 0);
    sgemm128k<<<dim3(2, MBLK, 1), 128>>>(x, Wi,    hi,    NN, 128, 0, 0, 0);
    sgemm128k<<<dim3(2, MBLK, 1), 128>>>(x, Wsn,   sn,    NN, 128, 0, 0, 0);
    sgemm128k<<<dim3(1, MBLK, 1), 128>>>(x, Wself, self_, NN,  32, 0, 0, 0);

    // pack qkv weights
    k_pack<<<(RR * HC * QKVP + 255) / 256, 256>>>(Wq, Wk, Wv);

    // counting sort of edges by segment
    k_zero<<<(RNSEG + 255) / 256, 256>>>();
    k_hist<<<(EE + 255) / 256, 256>>>(ei, et);
    k_scan1<<<NB1, 256>>>();
    k_scan2<<<1, 512>>>(NB1);
    k_scan3<<<(RNSEG + 255) / 256, 256>>>();
    k_scatter<<<(EE + 255) / 256, 256>>>(ei, et);

    // per-segment attention aggregation -> z
    k_agg<<<RNSEG / 8, 256>>>(natt);

    // batched qkv projection: for each r, z[r] @ wcat[r] -> qkv[r]
    sgemm128k<<<dim3(2, MBLK, RR), 128>>>(z, wcat, qkv, NN, QKVP,
                                          (long long)NN * HC,
                                          (long long)HC * QKVP,
                                          (long long)NN * QKVP);

    // relation attention + output
    k_final<<<(NN + 7) / 8, 256>>>(Wrel, out);
}

// round 10
// speedup vs baseline: 1.3792x; 1.3792x over previous
#include <cuda_runtime.h>
#include <cuda_bf16.h>
#include <cstdint>

// ---------------- problem constants (fixed by the dataset) ----------------
#define NN    50000
#define EE    640000
#define HH    4
#define CC    32
#define RR    8
#define HC    128           // H*C
#define RNSEG (RR*NN)       // 400000 segments
#define QKVP  96            // q|k|v packed columns
#define NODEP 416           // Wj|Wi|Wsn|Wself packed columns
#define NB1   391           // ceil(RNSEG/1024) scan blocks

// ---------------- device scratch (static: no runtime allocation) ----------
__device__ __align__(16) float          g_hj  [NN*HC];          // 25.6 MB
__device__ __align__(16) float          g_hi  [NN*HC];          // 25.6 MB
__device__ __align__(16) float          g_sn  [NN*HC];          // 25.6 MB
__device__ __align__(16) float          g_self[NN*CC];          //  6.4 MB
__device__ __align__(16) __nv_bfloat16  g_xh[NN*HC];            // x hi split
__device__ __align__(16) __nv_bfloat16  g_xl[NN*HC];            // x lo split
__device__ __align__(16) __nv_bfloat16  g_zh[(size_t)RR*NN*HC]; // z hi 51.2 MB
__device__ __align__(16) __nv_bfloat16  g_zl[(size_t)RR*NN*HC]; // z lo 51.2 MB
__device__ __align__(16) float          g_qkvb[(size_t)RR*NN*QKVP]; // 153.6 MB
__device__ __align__(16) __nv_bfloat16  g_wnh[NODEP*HC];        // node W^T hi [p][k]
__device__ __align__(16) __nv_bfloat16  g_wnl[NODEP*HC];        // node W^T lo
__device__ __align__(16) __nv_bfloat16  g_wqh[RR*QKVP*HC];      // qkv W^T hi [r][j][k]
__device__ __align__(16) __nv_bfloat16  g_wql[RR*QKVP*HC];      // qkv W^T lo
__device__ int   g_cnt   [RNSEG];
__device__ int   g_start [RNSEG];
__device__ int   g_cursor[RNSEG];
__device__ int   g_ssrc  [EE];
__device__ int   g_bsum  [512];
__device__ int   g_ei64;
__device__ int   g_et64;

// ---------------- helpers --------------------------------------------------
__device__ __forceinline__ uint32_t smem_u32(const void* p) {
    uint32_t a;
    asm("{ .reg .u64 t; cvta.to.shared.u64 t, %1; cvt.u32.u64 %0, t; }"
        : "=r"(a) : "l"(p));
    return a;
}

__device__ __forceinline__ void ldm_x4(uint32_t* r, uint32_t a) {
    asm volatile("ldmatrix.sync.aligned.m8n8.x4.shared.b16 {%0,%1,%2,%3}, [%4];"
                 : "=r"(r[0]), "=r"(r[1]), "=r"(r[2]), "=r"(r[3]) : "r"(a));
}

__device__ __forceinline__ void mma16816(float* c, const uint32_t* a, const uint32_t* b) {
    asm volatile(
        "mma.sync.aligned.m16n8k16.row.col.f32.bf16.bf16.f32 "
        "{%0,%1,%2,%3}, {%4,%5,%6,%7}, {%8,%9}, {%0,%1,%2,%3};"
        : "+f"(c[0]), "+f"(c[1]), "+f"(c[2]), "+f"(c[3])
        : "r"(a[0]), "r"(a[1]), "r"(a[2]), "r"(a[3]), "r"(b[0]), "r"(b[1]));
}

// ---------------- dtype sniffing -------------------------------------------
__global__ void k_detect(const int* __restrict__ ei_raw,
                         const int* __restrict__ et_raw)
{
    int a = 1, b = 1;
    for (int i = 0; i < 128; i++) {
        if (ei_raw[2 * i + 1] != 0) a = 0;
        if (et_raw[2 * i + 1] != 0) b = 0;
    }
    g_ei64 = a;
    g_et64 = b;
}

__device__ __forceinline__ int load_idx(const int* __restrict__ p, int i, int is64)
{
    return is64 ? p[2 * i] : p[i];
}

// ---------------- bf16 hi/lo split + weight packing ------------------------
__global__ void k_split_x(const float* __restrict__ x)
{
    int i = blockIdx.x * blockDim.x + threadIdx.x;
    if (i >= NN * HC) return;
    float v = x[i];
    __nv_bfloat16 h = __float2bfloat16(v);
    g_xh[i] = h;
    g_xl[i] = __float2bfloat16(v - __bfloat162float(h));
}

__global__ void k_packw(const float* __restrict__ Wj, const float* __restrict__ Wi,
                        const float* __restrict__ Wsn, const float* __restrict__ Wself)
{
    int i = blockIdx.x * blockDim.x + threadIdx.x;   // p*128 + k
    if (i >= NODEP * HC) return;
    int k = i & 127, p = i >> 7;
    float v;
    if      (p < 128) v = Wj  [k * 128 + p];
    else if (p < 256) v = Wi  [k * 128 + (p - 128)];
    else if (p < 384) v = Wsn [k * 128 + (p - 256)];
    else              v = Wself[k * 32 + (p - 384)];
    __nv_bfloat16 h = __float2bfloat16(v);
    g_wnh[i] = h;
    g_wnl[i] = __float2bfloat16(v - __bfloat162float(h));
}

__global__ void k_packq(const float* __restrict__ Wq, const float* __restrict__ Wk,
                        const float* __restrict__ Wv)
{
    int i = blockIdx.x * blockDim.x + threadIdx.x;   // r*96*128 + j*128 + k
    if (i >= RR * QKVP * HC) return;
    int k = i & 127;
    int j = (i >> 7) % QKVP;
    int r = i / (QKVP * HC);
    float v;
    if      (j < 32) v = Wq[((r * 128) + k) * 32 + j];
    else if (j < 64) v = Wk[((r * 128) + k) * 32 + (j - 32)];
    else             v = Wv[((r * 128) + k) * 32 + (j - 64)];
    __nv_bfloat16 h = __float2bfloat16(v);
    g_wqh[i] = h;
    g_wql[i] = __float2bfloat16(v - __bfloat162float(h));
}

// ---------------- bf16-split HMMA GEMM (mma.sync, sm_80-level PTX) ---------
// C[M,P] = (Ah+Al)[M,128] @ (Bh+Bl)^T, B stored [P][128] K-major (= col-major B).
// 3 passes: Ah*Bh + Al*Bh + Ah*Bl, fp32 accumulators.
// CTA 256 thr, tile 128x64, warp tile 32x32. Rows padded to 272 B in smem
// (stride 68 words -> 8-lane ldmatrix phases hit distinct bank quads).
#define ROWB   272
#define ASZ    (128 * ROWB)   // 34816
#define BSZ    (64  * ROWB)   // 17408
#define SM_TOT (2 * ASZ + 2 * BSZ)   // 104448

__global__ __launch_bounds__(256)
void tgemm(const __nv_bfloat16* __restrict__ Ah, const __nv_bfloat16* __restrict__ Al,
           const __nv_bfloat16* __restrict__ Bh, const __nv_bfloat16* __restrict__ Bl,
           float* __restrict__ C, int M, int Prows, int mode,
           long long sA, long long sB, long long sC)
{
    extern __shared__ __align__(16) char sm[];
    const int tid = threadIdx.x;
    const int l   = tid & 31, w = tid >> 5;
    const int wm  = w >> 1, wn = w & 1;          // warp grid 4 x 2
    const int m0  = blockIdx.y * 128;
    const int n0  = blockIdx.x * 64;
    Ah += (long long)blockIdx.z * sA;  Al += (long long)blockIdx.z * sA;
    Bh += (long long)blockIdx.z * sB;  Bl += (long long)blockIdx.z * sB;
    C  += (long long)blockIdx.z * sC;

    char* smA[2] = { sm, sm + ASZ };
    char* smB[2] = { sm + 2 * ASZ, sm + 2 * ASZ + BSZ };

    // ---- stage A hi/lo: 128 rows x 128 bf16, 16B chunks ----
    const uint4 z4 = make_uint4(0u, 0u, 0u, 0u);
    for (int i = tid; i < 2048; i += 256) {
        int row = i >> 4, c8 = i & 15;
        uint4 vh = z4, vl = z4;
        int gm = m0 + row;
        if (gm < M) {
            vh = *(const uint4*)(Ah + (size_t)gm * 128 + c8 * 8);
            vl = *(const uint4*)(Al + (size_t)gm * 128 + c8 * 8);
        }
        *(uint4*)(smA[0] + row * ROWB + c8 * 16) = vh;
        *(uint4*)(smA[1] + row * ROWB + c8 * 16) = vl;
    }
    // ---- stage B hi/lo: 64 rows x 128 bf16 ----
    for (int i = tid; i < 1024; i += 256) {
        int row = i >> 4, c8 = i & 15;
        uint4 vh = z4, vl = z4;
        int gp = n0 + row;
        if (gp < Prows) {
            vh = *(const uint4*)(Bh + (size_t)gp * 128 + c8 * 8);
            vl = *(const uint4*)(Bl + (size_t)gp * 128 + c8 * 8);
        }
        *(uint4*)(smB[0] + row * ROWB + c8 * 16) = vh;
        *(uint4*)(smB[1] + row * ROWB + c8 * 16) = vl;
    }
    __syncthreads();

    // ---- per-lane ldmatrix base addresses ----
    // A x4 tiles: {m0-7,k0-7},{m8-15,k0-7},{m0-7,k8-15},{m8-15,k8-15}
    //   lane: row = base + (l&15), colbyte = ((l>>4)<<4); +32B per k16 step
    // B x4 tiles: {n0-7,k0-7},{n0-7,k8-15},{n8-15,k0-7},{n8-15,k8-15}
    //   lane: row = base + ((l>>4)<<3) + (l&7), colbyte = (((l>>3)&1)<<4)
    uint32_t aAddr[2][2], bAddr[2][2];
#pragma unroll
    for (int s = 0; s < 2; s++) {
#pragma unroll
        for (int im = 0; im < 2; im++)
            aAddr[s][im] = smem_u32(smA[s] + (wm * 32 + im * 16 + (l & 15)) * ROWB
                                    + ((l >> 4) << 4));
#pragma unroll
        for (int g = 0; g < 2; g++)
            bAddr[s][g] = smem_u32(smB[s] + (wn * 32 + g * 16 + ((l >> 4) << 3) + (l & 7)) * ROWB
                                   + (((l >> 3) & 1) << 4));
    }

    float acc[2][4][4];
#pragma unroll
    for (int im = 0; im < 2; im++)
#pragma unroll
        for (int j = 0; j < 4; j++)
#pragma unroll
            for (int q = 0; q < 4; q++) acc[im][j][q] = 0.f;

#pragma unroll
    for (int c = 0; c < 8; c++) {
        uint32_t af[2][2][4], bf[2][8];
#pragma unroll
        for (int s = 0; s < 2; s++) {
#pragma unroll
            for (int im = 0; im < 2; im++)
                ldm_x4(af[s][im], aAddr[s][im] + (c << 5));
#pragma unroll
            for (int g = 0; g < 2; g++) {
                uint32_t t[4];
                ldm_x4(t, bAddr[s][g] + (c << 5));
                // tiles: t0=b0(n-tile 2g), t1=b1(2g), t2=b0(2g+1), t3=b1(2g+1)
                bf[s][4 * g + 0] = t[0]; bf[s][4 * g + 1] = t[1];
                bf[s][4 * g + 2] = t[2]; bf[s][4 * g + 3] = t[3];
            }
        }
        // pass (sa,sb): (0,0) hi*hi, (1,0) lo*hi, (0,1) hi*lo
#pragma unroll
        for (int im = 0; im < 2; im++)
#pragma unroll
            for (int j = 0; j < 4; j++) {
                mma16816(acc[im][j], af[0][im], &bf[0][2 * j]);
                mma16816(acc[im][j], af[1][im], &bf[0][2 * j]);
                mma16816(acc[im][j], af[0][im], &bf[1][2 * j]);
            }
    }

    // ---- epilogue: c-frag lane map: (g=l>>2, t=l&3):
    //   c0=C[g][2t] c1=C[g][2t+1] c2=C[g+8][2t] c3=C[g+8][2t+1]
    const int gq = l >> 2, tq = l & 3;
#pragma unroll
    for (int im = 0; im < 2; im++) {
#pragma unroll
        for (int j = 0; j < 4; j++) {
            int row = m0 + wm * 32 + im * 16 + gq;
            int col = n0 + wn * 32 + j * 8 + 2 * tq;
#pragma unroll
            for (int half = 0; half < 2; half++) {
                int rr = row + half * 8;
                if (rr >= M) continue;
                float v0 = acc[im][j][2 * half], v1 = acc[im][j][2 * half + 1];
                if (mode == 0) {
                    if (col < 128)
                        *(float2*)(g_hj + (size_t)rr * 128 + col) = make_float2(v0, v1);
                    else if (col < 256)
                        *(float2*)(g_hi + (size_t)rr * 128 + (col - 128)) = make_float2(v0, v1);
                    else if (col < 384)
                        *(float2*)(g_sn + (size_t)rr * 128 + (col - 256)) = make_float2(v0, v1);
                    else if (col < 416)
                        *(float2*)(g_self + (size_t)rr * 32 + (col - 384)) = make_float2(v0, v1);
                } else {
                    if (col < Prows)
                        *(float2*)(C + (size_t)rr * Prows + col) = make_float2(v0, v1);
                }
            }
        }
    }
}

// ---------------- counting sort of edges by segment ------------------------
__global__ void k_zero()
{
    int i = blockIdx.x * blockDim.x + threadIdx.x;
    if (i < RNSEG) { g_cnt[i] = 0; g_cursor[i] = 0; }
}

__global__ void k_hist(const int* __restrict__ ei, const int* __restrict__ et)
{
    int e = blockIdx.x * blockDim.x + threadIdx.x;
    if (e >= EE) return;
    int i64 = g_ei64, t64 = g_et64;
    int dst = load_idx(ei, EE + e, i64);
    int r   = load_idx(et, e, t64);
    atomicAdd(&g_cnt[r * NN + dst], 1);
}

__global__ void k_scan1()
{
    __shared__ int sh[256];
    int t = threadIdx.x;
    int base = blockIdx.x * 1024 + t * 4;
    int v0 = 0, v1 = 0, v2 = 0, v3 = 0;
    if (base + 0 < RNSEG) v0 = g_cnt[base + 0];
    if (base + 1 < RNSEG) v1 = g_cnt[base + 1];
    if (base + 2 < RNSEG) v2 = g_cnt[base + 2];
    if (base + 3 < RNSEG) v3 = g_cnt[base + 3];
    int local = v0 + v1 + v2 + v3;
    sh[t] = local;
    __syncthreads();
    for (int off = 1; off < 256; off <<= 1) {
        int x = 0;
        if (t >= off) x = sh[t - off];
        __syncthreads();
        if (t >= off) sh[t] += x;
        __syncthreads();
    }
    int run = sh[t] - local;
    if (base + 0 < RNSEG) g_start[base + 0] = run;  run += v0;
    if (base + 1 < RNSEG) g_start[base + 1] = run;  run += v1;
    if (base + 2 < RNSEG) g_start[base + 2] = run;  run += v2;
    if (base + 3 < RNSEG) g_start[base + 3] = run;
    if (t == 255) g_bsum[blockIdx.x] = sh[255];
}

__global__ void k_scan2(int nb)
{
    __shared__ int sh[512];
    int t = threadIdx.x;
    int val = (t < nb) ? g_bsum[t] : 0;
    sh[t] = val;
    __syncthreads();
    for (int off = 1; off < 512; off <<= 1) {
        int x = 0;
        if (t >= off) x = sh[t - off];
        __syncthreads();
        if (t >= off) sh[t] += x;
        __syncthreads();
    }
    if (t < nb) g_bsum[t] = sh[t] - val;
}

__global__ void k_scan3()
{
    int i = blockIdx.x * blockDim.x + threadIdx.x;
    if (i < RNSEG) g_start[i] += g_bsum[i >> 10];
}

__global__ void k_scatter(const int* __restrict__ ei, const int* __restrict__ et)
{
    int e = blockIdx.x * blockDim.x + threadIdx.x;
    if (e >= EE) return;
    int i64 = g_ei64, t64 = g_et64;
    int src = load_idx(ei, e, i64);
    int dst = load_idx(ei, EE + e, i64);
    int r   = load_idx(et, e, t64);
    int seg = r * NN + dst;
    int pos = g_start[seg] + atomicAdd(&g_cursor[seg], 1);
    g_ssrc[pos] = src;
}

// ---------------- per-segment softmax-weighted aggregation -----------------
// One warp per segment (r,n). Emits z = sn + sum a*h_j as bf16 hi/lo.
__global__ void k_agg(const float* __restrict__ natt)
{
    int w    = (blockIdx.x * blockDim.x + threadIdx.x) >> 5;
    int lane = threadIdx.x & 31;
    if (w >= RNSEG) return;
    int r  = w / NN;
    int n  = w - r * NN;
    int d0 = lane * 4;

    float4 sn4 = *(const float4*)(g_sn + (size_t)n * HC + d0);
    float4 acc = make_float4(0.f, 0.f, 0.f, 0.f);
    int cnt = g_cnt[w];

    if (cnt > 0) {
        int st = g_start[w];
        float4 xi = *(const float4*)(g_hi + (size_t)n * HC + d0);
        int h  = lane >> 3;
        int cb = (lane & 7) * 4;
        const float* ab = natt + (r * HH + h) * (2 * CC);
        float4 ai = *(const float4*)(ab + cb);
        float4 aj = *(const float4*)(ab + CC + cb);

        float pi = ai.x * xi.x + ai.y * xi.y + ai.z * xi.z + ai.w * xi.w;
        pi += __shfl_xor_sync(0xffffffffu, pi, 1);
        pi += __shfl_xor_sync(0xffffffffu, pi, 2);
        pi += __shfl_xor_sync(0xffffffffu, pi, 4);

        float denom = 0.f;
        for (int j = 0; j < cnt; j++) {
            int src = g_ssrc[st + j];
            float4 xj = *(const float4*)(g_hj + (size_t)src * HC + d0);
            float pj = aj.x * xj.x + aj.y * xj.y + aj.z * xj.z + aj.w * xj.w;
            pj += __shfl_xor_sync(0xffffffffu, pj, 1);
            pj += __shfl_xor_sync(0xffffffffu, pj, 2);
            pj += __shfl_xor_sync(0xffffffffu, pj, 4);
            float al = pi + pj;
            al = (al > 0.f) ? al : 0.2f * al;
            denom += __expf(al);
        }
        float inv = 1.f / (denom + 1e-16f);
        for (int j = 0; j < cnt; j++) {
            int src = g_ssrc[st + j];
            float4 xj = *(const float4*)(g_hj + (size_t)src * HC + d0);
            float pj = aj.x * xj.x + aj.y * xj.y + aj.z * xj.z + aj.w * xj.w;
            pj += __shfl_xor_sync(0xffffffffu, pj, 1);
            pj += __shfl_xor_sync(0xffffffffu, pj, 2);
            pj += __shfl_xor_sync(0xffffffffu, pj, 4);
            float al = pi + pj;
            al = (al > 0.f) ? al : 0.2f * al;
            float a = __expf(al) * inv;
            acc.x += a * xj.x; acc.y += a * xj.y;
            acc.z += a * xj.z; acc.w += a * xj.w;
        }
    }
    float zr[4] = { sn4.x + acc.x, sn4.y + acc.y, sn4.z + acc.z, sn4.w + acc.w };
    __nv_bfloat16 hh[4], ll[4];
#pragma unroll
    for (int t = 0; t < 4; t++) {
        hh[t] = __float2bfloat16(zr[t]);
        ll[t] = __float2bfloat16(zr[t] - __bfloat162float(hh[t]));
    }
    *(uint2*)(g_zh + (size_t)w * HC + d0) = *(uint2*)hh;
    *(uint2*)(g_zl + (size_t)w * HC + d0) = *(uint2*)ll;
}

// ---------------- relation-level attention + output ------------------------
__global__ void k_final(const float* __restrict__ wrel, float* __restrict__ out)
{
    int n    = (blockIdx.x * blockDim.x + threadIdx.x) >> 5;
    int lane = threadIdx.x & 31;
    if (n >= NN) return;

    float q[RR], kk[RR], vv[RR];
#pragma unroll
    for (int r = 0; r < RR; r++) {
        const float* p = g_qkvb + ((size_t)r * NN + n) * QKVP;
        q[r]  = p[lane];
        kk[r] = p[32 + lane];
        vv[r] = p[64 + lane];
    }
    float selfc = g_self[(size_t)n * CC + lane];
    float o = 0.f;

#pragma unroll
    for (int r = 0; r < RR; r++) {
        float t[RR];
#pragma unroll
        for (int s = 0; s < RR; s++) t[s] = q[r] * kk[s];
#pragma unroll
        for (int off = 16; off > 0; off >>= 1)
#pragma unroll
            for (int s = 0; s < RR; s++)
                t[s] += __shfl_xor_sync(0xffffffffu, t[s], off);
        float m = t[0];
#pragma unroll
        for (int s = 1; s < RR; s++) m = fmaxf(m, t[s]);
        float psum = 0.f, dacc = 0.f;
#pragma unroll
        for (int s = 0; s < RR; s++) {
            float e = __expf(t[s] - m);
            psum += e;
            dacc += e * vv[s];
        }
        float delta = dacc / psum;
        float sd = delta;
#pragma unroll
        for (int off = 16; off > 0; off >>= 1)
            sd += __shfl_xor_sync(0xffffffffu, sd, off);
        float mask = (sd != 0.f) ? 1.f : 0.f;
        o += (delta + selfc * mask) * wrel[r];
    }
    out[n * CC + lane] = o;
}

// ---------------- host launcher --------------------------------------------
extern "C" void kernel_launch(void* const* d_in, const int* in_sizes, int n_in,
                              void* d_out, int out_size)
{
    (void)in_sizes; (void)n_in; (void)out_size;
    const float* x    = (const float*)d_in[0];
    const int*   ei   = (const int*)d_in[1];    // int32 OR int64 (sniffed)
    const int*   et   = (const int*)d_in[2];
    const float* Wj   = (const float*)d_in[3];
    const float* Wi   = (const float*)d_in[4];
    const float* natt = (const float*)d_in[5];
    const float* Wq   = (const float*)d_in[6];
    const float* Wk   = (const float*)d_in[7];
    const float* Wv   = (const float*)d_in[8];
    const float* Wself= (const float*)d_in[9];
    const float* Wsn  = (const float*)d_in[10];
    const float* Wrel = (const float*)d_in[11];
    float*       out  = (float*)d_out;

    cudaFuncSetAttribute(tgemm, cudaFuncAttributeMaxDynamicSharedMemorySize, SM_TOT);

    void *xh, *xl, *zh, *zl, *qkv, *wnh, *wnl, *wqh, *wql;
    cudaGetSymbolAddress(&xh,  g_xh);   cudaGetSymbolAddress(&xl,  g_xl);
    cudaGetSymbolAddress(&zh,  g_zh);   cudaGetSymbolAddress(&zl,  g_zl);
    cudaGetSymbolAddress(&qkv, g_qkvb);
    cudaGetSymbolAddress(&wnh, g_wnh);  cudaGetSymbolAddress(&wnl, g_wnl);
    cudaGetSymbolAddress(&wqh, g_wqh);  cudaGetSymbolAddress(&wql, g_wql);

    const int MBLK = (NN + 127) / 128;   // 391

    // dtype sniff + input conversions
    k_detect<<<1, 1>>>(ei, et);
    k_split_x<<<(NN * HC + 255) / 256, 256>>>(x);
    k_packw<<<(NODEP * HC + 255) / 256, 256>>>(Wj, Wi, Wsn, Wself);
    k_packq<<<(RR * QKVP * HC + 255) / 256, 256>>>(Wq, Wk, Wv);

    // counting sort of edges by segment
    k_zero<<<(RNSEG + 255) / 256, 256>>>();
    k_hist<<<(EE + 255) / 256, 256>>>(ei, et);
    k_scan1<<<NB1, 256>>>();
    k_scan2<<<1, 512>>>(NB1);
    k_scan3<<<(RNSEG + 255) / 256, 256>>>();
    k_scatter<<<(EE + 255) / 256, 256>>>(ei, et);

    // fused node projections: [hj|hi|sn|self] = x @ [Wj|Wi|Wsn|Wself]
    tgemm<<<dim3(7, MBLK, 1), 256, SM_TOT>>>(
        (const __nv_bfloat16*)xh, (const __nv_bfloat16*)xl,
        (const __nv_bfloat16*)wnh, (const __nv_bfloat16*)wnl,
        nullptr, NN, NODEP, 0, 0, 0, 0);

    // per-segment attention aggregation -> z (bf16 hi/lo)
    k_agg<<<RNSEG / 8, 256>>>(natt);

    // batched qkv projection: q|k|v[r] = z[r] @ [Wq|Wk|Wv][r]
    tgemm<<<dim3(2, MBLK, RR), 256, SM_TOT>>>(
        (const __nv_bfloat16*)zh, (const __nv_bfloat16*)zl,
        (const __nv_bfloat16*)wqh, (const __nv_bfloat16*)wql,
        (float*)qkv, NN, QKVP, 1,
        (long long)NN * HC, (long long)QKVP * HC, (long long)NN * QKVP);

    // relation attention + output
    k_final<<<(NN + 7) / 8, 256>>>(Wrel, out);
}

// round 11
// speedup vs baseline: 1.7897x; 1.2976x over previous
#include <cuda_runtime.h>
#include <cuda_fp16.h>
#include <cstdint>

// ---------------- problem constants (fixed by the dataset) ----------------
#define NN    50000
#define EE    640000
#define HH    4
#define CC    32
#define RR    8
#define HC    128           // H*C
#define RNSEG (RR*NN)       // 400000 segments
#define QKVP  96            // q|k|v packed columns
#define NODEP 416           // Wj|Wi|Wsn|Wself packed columns
#define NB1   391           // ceil(RNSEG/1024) scan blocks

// ---------------- device scratch (static: no runtime allocation) ----------
__device__ __align__(16) float   g_hj  [NN*HC];            // 25.6 MB
__device__ __align__(16) float   g_hi  [NN*HC];            // 25.6 MB
__device__ __align__(16) float   g_sn  [NN*HC];            // 25.6 MB
__device__ __align__(16) float   g_self[NN*CC];            //  6.4 MB
__device__ __align__(16) __half  g_xh[NN*HC];              // x hi split
__device__ __align__(16) __half  g_xl[NN*HC];              // x lo split
__device__ __align__(16) __half  g_zh[(size_t)RR*NN*HC];   // z hi 51.2 MB
__device__ __align__(16) __half  g_zl[(size_t)RR*NN*HC];   // z lo 51.2 MB
__device__ __align__(16) float   g_qkvb[(size_t)RR*NN*QKVP]; // 153.6 MB
__device__ __align__(16) __half  g_wnh[NODEP*HC];          // node W^T fp16 [p][k]
__device__ __align__(16) __half  g_wqh[RR*QKVP*HC];        // qkv  W^T fp16 [r][j][k]
__device__ int   g_cnt   [RNSEG];
__device__ int   g_start [RNSEG];
__device__ int   g_cursor[RNSEG];
__device__ int   g_ssrc  [EE];
__device__ int   g_bsum  [512];
__device__ int   g_ei64;
__device__ int   g_et64;

// ---------------- helpers --------------------------------------------------
__device__ __forceinline__ uint32_t smem_u32(const void* p) {
    uint32_t a;
    asm("{ .reg .u64 t; cvta.to.shared.u64 t, %1; cvt.u32.u64 %0, t; }"
        : "=r"(a) : "l"(p));
    return a;
}

__device__ __forceinline__ void ldm_x4(uint32_t* r, uint32_t a) {
    asm volatile("ldmatrix.sync.aligned.m8n8.x4.shared.b16 {%0,%1,%2,%3}, [%4];"
                 : "=r"(r[0]), "=r"(r[1]), "=r"(r[2]), "=r"(r[3]) : "r"(a));
}

__device__ __forceinline__ void mma16816(float* c, const uint32_t* a, const uint32_t* b) {
    asm volatile(
        "mma.sync.aligned.m16n8k16.row.col.f32.f16.f16.f32 "
        "{%0,%1,%2,%3}, {%4,%5,%6,%7}, {%8,%9}, {%0,%1,%2,%3};"
        : "+f"(c[0]), "+f"(c[1]), "+f"(c[2]), "+f"(c[3])
        : "r"(a[0]), "r"(a[1]), "r"(a[2]), "r"(a[3]), "r"(b[0]), "r"(b[1]));
}

__device__ __forceinline__ void cpa16(uint32_t dst, const void* src, int sz) {
    asm volatile("cp.async.cg.shared.global [%0], [%1], 16, %2;"
                 :: "r"(dst), "l"(src), "r"(sz) : "memory");
}

// ---------------- dtype sniffing -------------------------------------------
__global__ void k_detect(const int* __restrict__ ei_raw,
                         const int* __restrict__ et_raw)
{
    int a = 1, b = 1;
    for (int i = 0; i < 128; i++) {
        if (ei_raw[2 * i + 1] != 0) a = 0;
        if (et_raw[2 * i + 1] != 0) b = 0;
    }
    g_ei64 = a;
    g_et64 = b;
}

__device__ __forceinline__ int load_idx(const int* __restrict__ p, int i, int is64)
{
    return is64 ? p[2 * i] : p[i];
}

// ---------------- fp16 hi/lo split + weight packing ------------------------
__global__ void k_split_x(const float* __restrict__ x)
{
    int i = blockIdx.x * blockDim.x + threadIdx.x;
    if (i >= NN * HC) return;
    float v = x[i];
    __half h = __float2half(v);
    g_xh[i] = h;
    g_xl[i] = __float2half(v - __half2float(h));
}

__global__ void k_packw(const float* __restrict__ Wj, const float* __restrict__ Wi,
                        const float* __restrict__ Wsn, const float* __restrict__ Wself)
{
    int i = blockIdx.x * blockDim.x + threadIdx.x;   // p*128 + k
    if (i >= NODEP * HC) return;
    int k = i & 127, p = i >> 7;
    float v;
    if      (p < 128) v = Wj  [k * 128 + p];
    else if (p < 256) v = Wi  [k * 128 + (p - 128)];
    else if (p < 384) v = Wsn [k * 128 + (p - 256)];
    else              v = Wself[k * 32 + (p - 384)];
    g_wnh[i] = __float2half(v);
}

__global__ void k_packq(const float* __restrict__ Wq, const float* __restrict__ Wk,
                        const float* __restrict__ Wv)
{
    int i = blockIdx.x * blockDim.x + threadIdx.x;   // r*96*128 + j*128 + k
    if (i >= RR * QKVP * HC) return;
    int k = i & 127;
    int j = (i >> 7) % QKVP;
    int r = i / (QKVP * HC);
    float v;
    if      (j < 32) v = Wq[((r * 128) + k) * 32 + j];
    else if (j < 64) v = Wk[((r * 128) + k) * 32 + (j - 32)];
    else             v = Wv[((r * 128) + k) * 32 + (j - 64)];
    g_wqh[i] = __float2half(v);
}

// ---------------- fp16-split HMMA GEMM (mma.sync, sm_80-level PTX) ---------
// C[M,P] = (Ah+Al)[M,128] @ Bh^T, B stored [P][128] K-major (= col-major B).
// 2 passes: Ah*Bh + Al*Bh, fp32 accumulators. Dropped A*Blo ~= 1 ulp fp16 of W.
// CTA 256 thr (8 warps), tile 128 x NT, warp tile 16 x NT (warps stack in M).
// Rows padded to 272 B in smem -> ldmatrix phases conflict-free.
#define ROWB   272
#define ASZ    (128 * ROWB)                 // per split: 34816

template<int NT, int MODE>
__global__ __launch_bounds__(256)
void tgemm(const __half* __restrict__ Ah, const __half* __restrict__ Al,
           const __half* __restrict__ Bh, float* __restrict__ C,
           int M, int Prows, long long sA, long long sB, long long sC)
{
    extern __shared__ __align__(16) char sm[];
    const int tid = threadIdx.x;
    const int l   = tid & 31, w = tid >> 5;
    const int m0  = blockIdx.y * 128;
    const int n0  = blockIdx.x * NT;
    Ah += (long long)blockIdx.z * sA;  Al += (long long)blockIdx.z * sA;
    Bh += (long long)blockIdx.z * sB;
    C  += (long long)blockIdx.z * sC;

    char* smA0 = sm;
    char* smA1 = sm + ASZ;
    char* smB  = sm + 2 * ASZ;
    const uint32_t sbA0 = smem_u32(smA0), sbA1 = smem_u32(smA1), sbB = smem_u32(smB);

    // ---- async stage A hi/lo (128 rows x 128 fp16) and B (NT rows) ----
    for (int i = tid; i < 2048; i += 256) {
        int row = i >> 4, c8 = i & 15;
        int gm = m0 + row;
        int ok = (gm < M);
        size_t off = (size_t)(ok ? gm : 0) * 128 + c8 * 8;
        int sz = ok ? 16 : 0;
        cpa16(sbA0 + row * ROWB + c8 * 16, Ah + off, sz);
        cpa16(sbA1 + row * ROWB + c8 * 16, Al + off, sz);
    }
    for (int i = tid; i < NT * 16; i += 256) {
        int row = i >> 4, c8 = i & 15;
        int gp = n0 + row;
        int ok = (gp < Prows);
        cpa16(sbB + row * ROWB + c8 * 16,
              Bh + (size_t)(ok ? gp : 0) * 128 + c8 * 8, ok ? 16 : 0);
    }
    asm volatile("cp.async.commit_group;" ::: "memory");
    asm volatile("cp.async.wait_group 0;" ::: "memory");
    __syncthreads();

    // ---- per-lane ldmatrix base addresses ----
    // A x4 (m16k16): lane row = w*16 + (l&15), colbyte = (l>>4)<<4
    // B x4 (n16k16): lane row = g*16 + ((l>>4)<<3) + (l&7), colbyte = ((l>>3)&1)<<4
    uint32_t aA0 = sbA0 + (w * 16 + (l & 15)) * ROWB + ((l >> 4) << 4);
    uint32_t aA1 = sbA1 + (w * 16 + (l & 15)) * ROWB + ((l >> 4) << 4);
    uint32_t aB[NT / 16];
#pragma unroll
    for (int g = 0; g < NT / 16; g++)
        aB[g] = sbB + (g * 16 + ((l >> 4) << 3) + (l & 7)) * ROWB + (((l >> 3) & 1) << 4);

    float acc[NT / 8][4];
#pragma unroll
    for (int j = 0; j < NT / 8; j++)
#pragma unroll
        for (int q = 0; q < 4; q++) acc[j][q] = 0.f;

#pragma unroll
    for (int c = 0; c < 8; c++) {
        uint32_t af0[4], af1[4], bf[NT / 16][4];
        ldm_x4(af0, aA0 + (c << 5));
        ldm_x4(af1, aA1 + (c << 5));
#pragma unroll
        for (int g = 0; g < NT / 16; g++)
            ldm_x4(bf[g], aB[g] + (c << 5));
        // x4 B tiles: t0,t1 = n-lo frags, t2,t3 = n-hi frags of the 16-n group
#pragma unroll
        for (int j = 0; j < NT / 8; j++) {
            const uint32_t* bb = &bf[j >> 1][2 * (j & 1)];
            mma16816(acc[j], af0, bb);
            mma16816(acc[j], af1, bb);
        }
    }

    // ---- epilogue: c-frag map (g=l>>2, t=l&3): c0=C[g][2t] c1=C[g][2t+1]
    //      c2=C[g+8][2t] c3=C[g+8][2t+1]
    const int gq = l >> 2, tq = l & 3;
#pragma unroll
    for (int j = 0; j < NT / 8; j++) {
        int col = n0 + j * 8 + 2 * tq;
#pragma unroll
        for (int half = 0; half < 2; half++) {
            int rr = m0 + w * 16 + gq + half * 8;
            if (rr >= M) continue;
            float2 v = make_float2(acc[j][2 * half], acc[j][2 * half + 1]);
            if (MODE == 0) {
                if (col < 128)
                    *(float2*)(g_hj + (size_t)rr * 128 + col) = v;
                else if (col < 256)
                    *(float2*)(g_hi + (size_t)rr * 128 + (col - 128)) = v;
                else if (col < 384)
                    *(float2*)(g_sn + (size_t)rr * 128 + (col - 256)) = v;
                else if (col < 416)
                    *(float2*)(g_self + (size_t)rr * 32 + (col - 384)) = v;
            } else {
                if (col < Prows)
                    *(float2*)(C + (size_t)rr * Prows + col) = v;
            }
        }
    }
}

// ---------------- counting sort of edges by segment ------------------------
__global__ void k_zero()
{
    int i = blockIdx.x * blockDim.x + threadIdx.x;
    if (i < RNSEG) { g_cnt[i] = 0; g_cursor[i] = 0; }
}

__global__ void k_hist(const int* __restrict__ ei, const int* __restrict__ et)
{
    int e = blockIdx.x * blockDim.x + threadIdx.x;
    if (e >= EE) return;
    int i64 = g_ei64, t64 = g_et64;
    int dst = load_idx(ei, EE + e, i64);
    int r   = load_idx(et, e, t64);
    atomicAdd(&g_cnt[r * NN + dst], 1);
}

__global__ void k_scan1()
{
    __shared__ int sh[256];
    int t = threadIdx.x;
    int base = blockIdx.x * 1024 + t * 4;
    int v0 = 0, v1 = 0, v2 = 0, v3 = 0;
    if (base + 0 < RNSEG) v0 = g_cnt[base + 0];
    if (base + 1 < RNSEG) v1 = g_cnt[base + 1];
    if (base + 2 < RNSEG) v2 = g_cnt[base + 2];
    if (base + 3 < RNSEG) v3 = g_cnt[base + 3];
    int local = v0 + v1 + v2 + v3;
    sh[t] = local;
    __syncthreads();
    for (int off = 1; off < 256; off <<= 1) {
        int x = 0;
        if (t >= off) x = sh[t - off];
        __syncthreads();
        if (t >= off) sh[t] += x;
        __syncthreads();
    }
    int run = sh[t] - local;
    if (base + 0 < RNSEG) g_start[base + 0] = run;  run += v0;
    if (base + 1 < RNSEG) g_start[base + 1] = run;  run += v1;
    if (base + 2 < RNSEG) g_start[base + 2] = run;  run += v2;
    if (base + 3 < RNSEG) g_start[base + 3] = run;
    if (t == 255) g_bsum[blockIdx.x] = sh[255];
}

__global__ void k_scan2(int nb)
{
    __shared__ int sh[512];
    int t = threadIdx.x;
    int val = (t < nb) ? g_bsum[t] : 0;
    sh[t] = val;
    __syncthreads();
    for (int off = 1; off < 512; off <<= 1) {
        int x = 0;
        if (t >= off) x = sh[t - off];
        __syncthreads();
        if (t >= off) sh[t] += x;
        __syncthreads();
    }
    if (t < nb) g_bsum[t] = sh[t] - val;
}

__global__ void k_scan3()
{
    int i = blockIdx.x * blockDim.x + threadIdx.x;
    if (i < RNSEG) g_start[i] += g_bsum[i >> 10];
}

__global__ void k_scatter(const int* __restrict__ ei, const int* __restrict__ et)
{
    int e = blockIdx.x * blockDim.x + threadIdx.x;
    if (e >= EE) return;
    int i64 = g_ei64, t64 = g_et64;
    int src = load_idx(ei, e, i64);
    int dst = load_idx(ei, EE + e, i64);
    int r   = load_idx(et, e, t64);
    int seg = r * NN + dst;
    int pos = g_start[seg] + atomicAdd(&g_cursor[seg], 1);
    g_ssrc[pos] = src;
}

// ---------------- per-segment softmax-weighted aggregation -----------------
// One warp per segment (r,n). Emits z = sn + sum a*h_j as fp16 hi/lo.
__global__ void k_agg(const float* __restrict__ natt)
{
    int w    = (blockIdx.x * blockDim.x + threadIdx.x) >> 5;
    int lane = threadIdx.x & 31;
    if (w >= RNSEG) return;
    int r  = w / NN;
    int n  = w - r * NN;
    int d0 = lane * 4;

    float4 sn4 = *(const float4*)(g_sn + (size_t)n * HC + d0);
    float4 acc = make_float4(0.f, 0.f, 0.f, 0.f);
    int cnt = g_cnt[w];

    if (cnt > 0) {
        int st = g_start[w];
        float4 xi = *(const float4*)(g_hi + (size_t)n * HC + d0);
        int h  = lane >> 3;
        int cb = (lane & 7) * 4;
        const float* ab = natt + (r * HH + h) * (2 * CC);
        float4 ai = *(const float4*)(ab + cb);
        float4 aj = *(const float4*)(ab + CC + cb);

        float pi = ai.x * xi.x + ai.y * xi.y + ai.z * xi.z + ai.w * xi.w;
        pi += __shfl_xor_sync(0xffffffffu, pi, 1);
        pi += __shfl_xor_sync(0xffffffffu, pi, 2);
        pi += __shfl_xor_sync(0xffffffffu, pi, 4);

        float denom = 0.f;
        for (int j = 0; j < cnt; j++) {
            int src = g_ssrc[st + j];
            float4 xj = *(const float4*)(g_hj + (size_t)src * HC + d0);
            float pj = aj.x * xj.x + aj.y * xj.y + aj.z * xj.z + aj.w * xj.w;
            pj += __shfl_xor_sync(0xffffffffu, pj, 1);
            pj += __shfl_xor_sync(0xffffffffu, pj, 2);
            pj += __shfl_xor_sync(0xffffffffu, pj, 4);
            float al = pi + pj;
            al = (al > 0.f) ? al : 0.2f * al;
            denom += __expf(al);
        }
        float inv = 1.f / (denom + 1e-16f);
        for (int j = 0; j < cnt; j++) {
            int src = g_ssrc[st + j];
            float4 xj = *(const float4*)(g_hj + (size_t)src * HC + d0);
            float pj = aj.x * xj.x + aj.y * xj.y + aj.z * xj.z + aj.w * xj.w;
            pj += __shfl_xor_sync(0xffffffffu, pj, 1);
            pj += __shfl_xor_sync(0xffffffffu, pj, 2);
            pj += __shfl_xor_sync(0xffffffffu, pj, 4);
            float al = pi + pj;
            al = (al > 0.f) ? al : 0.2f * al;
            float a = __expf(al) * inv;
            acc.x += a * xj.x; acc.y += a * xj.y;
            acc.z += a * xj.z; acc.w += a * xj.w;
        }
    }
    float zr[4] = { sn4.x + acc.x, sn4.y + acc.y, sn4.z + acc.z, sn4.w + acc.w };
    __half hh[4], ll[4];
#pragma unroll
    for (int t = 0; t < 4; t++) {
        hh[t] = __float2half(zr[t]);
        ll[t] = __float2half(zr[t] - __half2float(hh[t]));
    }
    *(uint2*)(g_zh + (size_t)w * HC + d0) = *(uint2*)hh;
    *(uint2*)(g_zl + (size_t)w * HC + d0) = *(uint2*)ll;
}

// ---------------- relation-level attention + output ------------------------
__global__ void k_final(const float* __restrict__ wrel, float* __restrict__ out)
{
    int n    = (blockIdx.x * blockDim.x + threadIdx.x) >> 5;
    int lane = threadIdx.x & 31;
    if (n >= NN) return;

    float q[RR], kk[RR], vv[RR];
#pragma unroll
    for (int r = 0; r < RR; r++) {
        const float* p = g_qkvb + ((size_t)r * NN + n) * QKVP;
        q[r]  = p[lane];
        kk[r] = p[32 + lane];
        vv[r] = p[64 + lane];
    }
    float selfc = g_self[(size_t)n * CC + lane];
    float o = 0.f;

#pragma unroll
    for (int r = 0; r < RR; r++) {
        float t[RR];
#pragma unroll
        for (int s = 0; s < RR; s++) t[s] = q[r] * kk[s];
#pragma unroll
        for (int off = 16; off > 0; off >>= 1)
#pragma unroll
            for (int s = 0; s < RR; s++)
                t[s] += __shfl_xor_sync(0xffffffffu, t[s], off);
        float m = t[0];
#pragma unroll
        for (int s = 1; s < RR; s++) m = fmaxf(m, t[s]);
        float psum = 0.f, dacc = 0.f;
#pragma unroll
        for (int s = 0; s < RR; s++) {
            float e = __expf(t[s] - m);
            psum += e;
            dacc += e * vv[s];
        }
        float delta = dacc / psum;
        float sd = delta;
#pragma unroll
        for (int off = 16; off > 0; off >>= 1)
            sd += __shfl_xor_sync(0xffffffffu, sd, off);
        float mask = (sd != 0.f) ? 1.f : 0.f;
        o += (delta + selfc * mask) * wrel[r];
    }
    out[n * CC + lane] = o;
}

// ---------------- host launcher --------------------------------------------
extern "C" void kernel_launch(void* const* d_in, const int* in_sizes, int n_in,
                              void* d_out, int out_size)
{
    (void)in_sizes; (void)n_in; (void)out_size;
    const float* x    = (const float*)d_in[0];
    const int*   ei   = (const int*)d_in[1];    // int32 OR int64 (sniffed)
    const int*   et   = (const int*)d_in[2];
    const float* Wj   = (const float*)d_in[3];
    const float* Wi   = (const float*)d_in[4];
    const float* natt = (const float*)d_in[5];
    const float* Wq   = (const float*)d_in[6];
    const float* Wk   = (const float*)d_in[7];
    const float* Wv   = (const float*)d_in[8];
    const float* Wself= (const float*)d_in[9];
    const float* Wsn  = (const float*)d_in[10];
    const float* Wrel = (const float*)d_in[11];
    float*       out  = (float*)d_out;

    const int SM_NODE = 2 * ASZ + 64 * ROWB;   // 87040
    const int SM_QKV  = 2 * ASZ + 96 * ROWB;   // 95744
    cudaFuncSetAttribute(tgemm<64, 0>, cudaFuncAttributeMaxDynamicSharedMemorySize, SM_NODE);
    cudaFuncSetAttribute(tgemm<96, 1>, cudaFuncAttributeMaxDynamicSharedMemorySize, SM_QKV);

    void *xh, *xl, *zh, *zl, *qkv, *wnh, *wqh;
    cudaGetSymbolAddress(&xh,  g_xh);   cudaGetSymbolAddress(&xl,  g_xl);
    cudaGetSymbolAddress(&zh,  g_zh);   cudaGetSymbolAddress(&zl,  g_zl);
    cudaGetSymbolAddress(&qkv, g_qkvb);
    cudaGetSymbolAddress(&wnh, g_wnh);  cudaGetSymbolAddress(&wqh, g_wqh);

    const int MBLK = (NN + 127) / 128;   // 391

    // dtype sniff + input conversions
    k_detect<<<1, 1>>>(ei, et);
    k_split_x<<<(NN * HC + 255) / 256, 256>>>(x);
    k_packw<<<(NODEP * HC + 255) / 256, 256>>>(Wj, Wi, Wsn, Wself);
    k_packq<<<(RR * QKVP * HC + 255) / 256, 256>>>(Wq, Wk, Wv);

    // counting sort of edges by segment
    k_zero<<<(RNSEG + 255) / 256, 256>>>();
    k_hist<<<(EE + 255) / 256, 256>>>(ei, et);
    k_scan1<<<NB1, 256>>>();
    k_scan2<<<1, 512>>>(NB1);
    k_scan3<<<(RNSEG + 255) / 256, 256>>>();
    k_scatter<<<(EE + 255) / 256, 256>>>(ei, et);

    // fused node projections: [hj|hi|sn|self] = x @ [Wj|Wi|Wsn|Wself]
    tgemm<64, 0><<<dim3(7, MBLK, 1), 256, SM_NODE>>>(
        (const __half*)xh, (const __half*)xl, (const __half*)wnh,
        nullptr, NN, NODEP, 0, 0, 0);

    // per-segment attention aggregation -> z (fp16 hi/lo)
    k_agg<<<RNSEG / 8, 256>>>(natt);

    // batched qkv projection: q|k|v[r] = z[r] @ [Wq|Wk|Wv][r] (exact 96-col tile)
    tgemm<96, 1><<<dim3(1, MBLK, RR), 256, SM_QKV>>>(
        (const __half*)zh, (const __half*)zl, (const __half*)wqh,
        (float*)qkv, NN, QKVP,
        (long long)NN * HC, (long long)QKVP * HC, (long long)NN * QKVP);

    // relation attention + output
    k_final<<<(NN + 7) / 8, 256>>>(Wrel, out);
}